// round 2
// baseline (speedup 1.0000x reference)
#include <cuda_runtime.h>
#include <math.h>

// ---------------------------------------------------------------------------
// Problem constants: D=512, H=8, hd=64. T is runtime (6144 for the fixed setup).
// ---------------------------------------------------------------------------
#define MAX_T 8192
#define MAX_TILES 1024

// Scratch (device globals; no allocation allowed)
__device__ float g_qk [MAX_T * 1024];  // [T, 1024]: q = [:,0:512], k = [:,512:1024]
__device__ float g_v  [MAX_T * 512];
__device__ float g_ctx[MAX_T * 512];
__device__ float g_tmp[MAX_T * 512];
__device__ float g_h1 [MAX_T * 512];
__device__ float g_mid[MAX_T * 2048];
__device__ int   g_tiles[MAX_TILES * 4]; // (qstart, qlen, kstart, klen)
__device__ int   g_meta[4];              // [0] = ntiles

// ---------------------------------------------------------------------------
// Tile table builder. Detects int32 vs int64 cumsum (little-endian: int64 has
// zero high words, and cum[1] > 0 always, so raw32[1]==0 <=> int64).
// ---------------------------------------------------------------------------
__global__ void build_tiles_kernel(const int* __restrict__ cum_raw, int T) {
    bool is64 = (cum_raw[1] == 0);
    int nt = 0;
    for (int s = 0; s < 256; ++s) {
        int start = is64 ? cum_raw[2 * s] : cum_raw[s];
        if (start >= T) break;
        int end = is64 ? cum_raw[2 * (s + 1)] : cum_raw[s + 1];
        int len = end - start;
        for (int q0 = 0; q0 < len && nt < MAX_TILES; q0 += 64) {
            g_tiles[nt * 4 + 0] = start + q0;
            g_tiles[nt * 4 + 1] = min(64, len - q0);
            g_tiles[nt * 4 + 2] = start;
            g_tiles[nt * 4 + 3] = len;
            ++nt;
        }
        if (end >= T) break;
    }
    g_meta[0] = nt;
}

// ---------------------------------------------------------------------------
// Tiled SGEMM: C[M,N] = A[M,K] @ B[K,N] + bias[N]  (+ epilogue)
// EPI: 0 = bias; 1 = bias + exact GELU; 2 = bias + residual add
// BM=BN=128, BK=16, 256 threads, 8x8 per-thread micro-tile.
// Requires N % 128 == 0, K % 16 == 0 (true here: N in {512,1024,2048}).
// ---------------------------------------------------------------------------
template <int EPI>
__global__ void __launch_bounds__(256)
gemm128_kernel(const float* __restrict__ A, const float* __restrict__ B,
               const float* __restrict__ bias, const float* __restrict__ res,
               float* __restrict__ C, int M, int N, int K) {
    __shared__ float As[16][128];
    __shared__ float Bs[16][128];

    const int tid = threadIdx.x;
    const int tx  = tid & 15;
    const int ty  = tid >> 4;
    const int bm  = blockIdx.y * 128;
    const int bn  = blockIdx.x * 128;

    float acc[8][8];
#pragma unroll
    for (int i = 0; i < 8; ++i)
#pragma unroll
        for (int j = 0; j < 8; ++j) acc[i][j] = 0.f;

    for (int k0 = 0; k0 < K; k0 += 16) {
        // Load A tile (128x16), store transposed As[k][m]
#pragma unroll
        for (int p = 0; p < 2; ++p) {
            int l4  = tid + p * 256;      // 0..511 float4 slots
            int row = l4 >> 2;            // 0..127
            int kc  = (l4 & 3) * 4;       // 0,4,8,12
            float4 v = make_float4(0.f, 0.f, 0.f, 0.f);
            int gr = bm + row;
            if (gr < M) v = *(const float4*)(A + (size_t)gr * K + k0 + kc);
            As[kc + 0][row] = v.x;
            As[kc + 1][row] = v.y;
            As[kc + 2][row] = v.z;
            As[kc + 3][row] = v.w;
        }
        // Load B tile (16x128) directly
#pragma unroll
        for (int p = 0; p < 2; ++p) {
            int l4 = tid + p * 256;
            int kr = l4 >> 5;             // 0..15
            int nc = (l4 & 31) * 4;       // 0..124
            float4 v = *(const float4*)(B + (size_t)(k0 + kr) * N + bn + nc);
            *(float4*)&Bs[kr][nc] = v;
        }
        __syncthreads();

#pragma unroll
        for (int k = 0; k < 16; ++k) {
            float a[8], bb[8];
            *(float4*)(a)      = *(const float4*)&As[k][ty * 8];
            *(float4*)(a + 4)  = *(const float4*)&As[k][ty * 8 + 4];
            *(float4*)(bb)     = *(const float4*)&Bs[k][tx * 8];
            *(float4*)(bb + 4) = *(const float4*)&Bs[k][tx * 8 + 4];
#pragma unroll
            for (int i = 0; i < 8; ++i)
#pragma unroll
                for (int j = 0; j < 8; ++j) acc[i][j] += a[i] * bb[j];
        }
        __syncthreads();
    }

    // Epilogue
#pragma unroll
    for (int i = 0; i < 8; ++i) {
        int gr = bm + ty * 8 + i;
        if (gr >= M) continue;
#pragma unroll
        for (int j = 0; j < 8; ++j) {
            int gc = bn + tx * 8 + j;
            float c = acc[i][j] + bias[gc];
            if (EPI == 1) {
                c = 0.5f * c * (1.0f + erff(c * 0.70710678118654752f));
            } else if (EPI == 2) {
                c += res[(size_t)gr * N + gc];
            }
            C[(size_t)gr * N + gc] = c;
        }
    }
}

// ---------------------------------------------------------------------------
// Flash-style attention. One block = (one q-tile of <=64 rows, one head).
// QT=64, KT=32, hd=64. 256 threads as 16x16; thread owns 4 q-rows x 4 d-cols
// of O, and 4x2 of each S tile. Online softmax; row reductions across the
// 16 tx lanes via shfl_xor (half-warp safe: masks 1,2,4,8).
// ---------------------------------------------------------------------------
__global__ void __launch_bounds__(256)
attn_kernel(const float* __restrict__ qk, const float* __restrict__ v,
            float* __restrict__ ctx) {
    const int tile = blockIdx.x;
    if (tile >= g_meta[0]) return;
    const int h = blockIdx.y;

    const int qstart = g_tiles[tile * 4 + 0];
    const int qlen   = g_tiles[tile * 4 + 1];
    const int kstart = g_tiles[tile * 4 + 2];
    const int klen   = g_tiles[tile * 4 + 3];

    __shared__ float Qs[64][64];
    __shared__ float Ks[32][65];
    __shared__ float Vs[32][64];
    __shared__ float Ps[64][33];

    const int tid = threadIdx.x;
    const int tx  = tid & 15;
    const int ty  = tid >> 4;
    const int r0  = ty * 4;
    const int c0  = tx * 2;

    // Load Q tile (rows beyond qlen zeroed)
#pragma unroll
    for (int p = 0; p < 4; ++p) {
        int l4 = tid + p * 256;       // 0..1023
        int r  = l4 >> 4;             // 0..63
        int dc = (l4 & 15) * 4;       // 0..60
        float4 qv = make_float4(0.f, 0.f, 0.f, 0.f);
        if (r < qlen)
            qv = *(const float4*)(qk + (size_t)(qstart + r) * 1024 + h * 64 + dc);
        *(float4*)&Qs[r][dc] = qv;
    }

    float o[4][4];
    float m[4], l[4];
#pragma unroll
    for (int i = 0; i < 4; ++i) {
        m[i] = -1e30f; l[i] = 0.f;
#pragma unroll
        for (int j = 0; j < 4; ++j) o[i][j] = 0.f;
    }

    for (int kb = 0; kb < klen; kb += 32) {
        const int kn = min(32, klen - kb);
        // Load K,V blocks (32x64 each)
#pragma unroll
        for (int p = 0; p < 2; ++p) {
            int l4 = tid + p * 256;   // 0..511
            int r  = l4 >> 4;         // 0..31
            int dc = (l4 & 15) * 4;
            float4 kv = make_float4(0.f, 0.f, 0.f, 0.f);
            float4 vv = make_float4(0.f, 0.f, 0.f, 0.f);
            if (r < kn) {
                size_t t = (size_t)(kstart + kb + r);
                kv = *(const float4*)(qk + t * 1024 + 512 + h * 64 + dc);
                vv = *(const float4*)(v  + t * 512 + h * 64 + dc);
            }
            Ks[r][dc + 0] = kv.x; Ks[r][dc + 1] = kv.y;
            Ks[r][dc + 2] = kv.z; Ks[r][dc + 3] = kv.w;
            *(float4*)&Vs[r][dc] = vv;
        }
        __syncthreads();

        // S = Q @ K^T  (per thread: 4 rows x 2 keys)
        float s[4][2];
#pragma unroll
        for (int i = 0; i < 4; ++i) { s[i][0] = 0.f; s[i][1] = 0.f; }
#pragma unroll
        for (int d = 0; d < 64; d += 4) {
            float qv[4][4];
#pragma unroll
            for (int i = 0; i < 4; ++i)
                *(float4*)qv[i] = *(const float4*)&Qs[r0 + i][d];
            float k0v[4], k1v[4];
#pragma unroll
            for (int dd = 0; dd < 4; ++dd) {
                k0v[dd] = Ks[c0 + 0][d + dd];
                k1v[dd] = Ks[c0 + 1][d + dd];
            }
#pragma unroll
            for (int dd = 0; dd < 4; ++dd)
#pragma unroll
                for (int i = 0; i < 4; ++i) {
                    s[i][0] += qv[i][dd] * k0v[dd];
                    s[i][1] += qv[i][dd] * k1v[dd];
                }
        }

        // Online softmax per row
#pragma unroll
        for (int i = 0; i < 4; ++i) {
            float s0 = s[i][0] * 0.125f;
            float s1 = s[i][1] * 0.125f;
            if (kb + c0 + 0 >= klen) s0 = -1e30f;
            if (kb + c0 + 1 >= klen) s1 = -1e30f;
            float mb = fmaxf(s0, s1);
#pragma unroll
            for (int off = 8; off; off >>= 1)
                mb = fmaxf(mb, __shfl_xor_sync(0xffffffffu, mb, off));
            float mnew  = fmaxf(m[i], mb);
            float alpha = __expf(m[i] - mnew);
            float p0 = __expf(s0 - mnew);
            float p1 = __expf(s1 - mnew);
            float lb = p0 + p1;
#pragma unroll
            for (int off = 8; off; off >>= 1)
                lb += __shfl_xor_sync(0xffffffffu, lb, off);
            l[i] = l[i] * alpha + lb;
            m[i] = mnew;
#pragma unroll
            for (int j = 0; j < 4; ++j) o[i][j] *= alpha;
            Ps[r0 + i][c0 + 0] = p0;
            Ps[r0 + i][c0 + 1] = p1;
        }
        __syncthreads();

        // O += P @ V  (per thread: 4 rows x 4 d-cols)
#pragma unroll
        for (int k = 0; k < 32; ++k) {
            float4 vv = *(const float4*)&Vs[k][tx * 4];
            float p0 = Ps[r0 + 0][k];
            float p1 = Ps[r0 + 1][k];
            float p2 = Ps[r0 + 2][k];
            float p3 = Ps[r0 + 3][k];
            o[0][0] += p0 * vv.x; o[0][1] += p0 * vv.y; o[0][2] += p0 * vv.z; o[0][3] += p0 * vv.w;
            o[1][0] += p1 * vv.x; o[1][1] += p1 * vv.y; o[1][2] += p1 * vv.z; o[1][3] += p1 * vv.w;
            o[2][0] += p2 * vv.x; o[2][1] += p2 * vv.y; o[2][2] += p2 * vv.z; o[2][3] += p2 * vv.w;
            o[3][0] += p3 * vv.x; o[3][1] += p3 * vv.y; o[3][2] += p3 * vv.z; o[3][3] += p3 * vv.w;
        }
        __syncthreads();
    }

    // Write ctx (only valid query rows)
#pragma unroll
    for (int i = 0; i < 4; ++i) {
        int r = r0 + i;
        if (r < qlen) {
            float inv = 1.0f / l[i];
            float4 out = make_float4(o[i][0] * inv, o[i][1] * inv,
                                     o[i][2] * inv, o[i][3] * inv);
            *(float4*)(ctx + (size_t)(qstart + r) * 512 + h * 64 + tx * 4) = out;
        }
    }
}

// ---------------------------------------------------------------------------
// Row-wise LayerNorm over D=512. One block per row, 256 threads.
// ---------------------------------------------------------------------------
__global__ void __launch_bounds__(256)
ln_kernel(const float* __restrict__ x, const float* __restrict__ g,
          const float* __restrict__ b, float* __restrict__ y) {
    const int row = blockIdx.x;
    const int tid = threadIdx.x;
    const float* xr = x + (size_t)row * 512;
    float v0 = xr[tid], v1 = xr[tid + 256];
    float s = v0 + v1;
    float q = v0 * v0 + v1 * v1;
#pragma unroll
    for (int off = 16; off; off >>= 1) {
        s += __shfl_xor_sync(0xffffffffu, s, off);
        q += __shfl_xor_sync(0xffffffffu, q, off);
    }
    __shared__ float ss[8], sq[8];
    int w = tid >> 5;
    if ((tid & 31) == 0) { ss[w] = s; sq[w] = q; }
    __syncthreads();
    if (tid < 32) {
        float s2 = (tid < 8) ? ss[tid] : 0.f;
        float q2 = (tid < 8) ? sq[tid] : 0.f;
#pragma unroll
        for (int off = 4; off; off >>= 1) {
            s2 += __shfl_xor_sync(0xffffffffu, s2, off);
            q2 += __shfl_xor_sync(0xffffffffu, q2, off);
        }
        if (tid == 0) { ss[0] = s2; sq[0] = q2; }
    }
    __syncthreads();
    float mean = ss[0] * (1.0f / 512.0f);
    float var  = sq[0] * (1.0f / 512.0f) - mean * mean;
    float rstd = rsqrtf(var + 1e-5f);
    y[(size_t)row * 512 + tid]       = (v0 - mean) * rstd * g[tid]       + b[tid];
    y[(size_t)row * 512 + tid + 256] = (v1 - mean) * rstd * g[tid + 256] + b[tid + 256];
}

// ---------------------------------------------------------------------------
// Launch
// ---------------------------------------------------------------------------
extern "C" void kernel_launch(void* const* d_in, const int* in_sizes, int n_in,
                              void* d_out, int out_size) {
    const float* h_n     = (const float*)d_in[0];
    const float* to_v_w  = (const float*)d_in[1];
    const float* to_v_b  = (const float*)d_in[2];
    const float* to_qk_w = (const float*)d_in[3];
    const float* to_qk_b = (const float*)d_in[4];
    const float* proj_w  = (const float*)d_in[5];
    const float* proj_b  = (const float*)d_in[6];
    const float* ffn_w1  = (const float*)d_in[7];
    const float* ffn_b1  = (const float*)d_in[8];
    const float* ffn_w2  = (const float*)d_in[9];
    const float* ffn_b2  = (const float*)d_in[10];
    const float* ln1_g   = (const float*)d_in[11];
    const float* ln1_b   = (const float*)d_in[12];
    const float* ln2_g   = (const float*)d_in[13];
    const float* ln2_b   = (const float*)d_in[14];
    const int*   cum     = (const int*)d_in[15];

    const int T = in_sizes[0] / 512;
    if (T <= 0 || T > MAX_T) return;

    float *qk, *v, *ctx, *tmp, *h1, *mid;
    cudaGetSymbolAddress((void**)&qk,  g_qk);
    cudaGetSymbolAddress((void**)&v,   g_v);
    cudaGetSymbolAddress((void**)&ctx, g_ctx);
    cudaGetSymbolAddress((void**)&tmp, g_tmp);
    cudaGetSymbolAddress((void**)&h1,  g_h1);
    cudaGetSymbolAddress((void**)&mid, g_mid);

    const int MB = (T + 127) / 128;

    // 0) tile table for ragged attention
    build_tiles_kernel<<<1, 1>>>(cum, T);

    // 1) v = h_n @ to_v_w + b ; qk = h_n @ to_qk_w + b
    gemm128_kernel<0><<<dim3(512 / 128, MB), 256>>>(h_n, to_v_w, to_v_b, nullptr, v, T, 512, 512);
    gemm128_kernel<0><<<dim3(1024 / 128, MB), 256>>>(h_n, to_qk_w, to_qk_b, nullptr, qk, T, 1024, 512);

    // 2) attention
    {
        int gx = (T + 63) / 64 + 64;  // upper bound incl. boundary fragmentation
        attn_kernel<<<dim3(gx, 8), 256>>>(qk, v, ctx);
    }

    // 3) tmp = h_n + ctx @ proj_w + proj_b ; h1 = LN1(tmp)
    gemm128_kernel<2><<<dim3(512 / 128, MB), 256>>>(ctx, proj_w, proj_b, h_n, tmp, T, 512, 512);
    ln_kernel<<<T, 256>>>(tmp, ln1_g, ln1_b, h1);

    // 4) mid = gelu(h1 @ ffn_w1 + b1)
    gemm128_kernel<1><<<dim3(2048 / 128, MB), 256>>>(h1, ffn_w1, ffn_b1, nullptr, mid, T, 2048, 512);

    // 5) tmp = h1 + mid @ ffn_w2 + b2 ; out = LN2(tmp)
    gemm128_kernel<2><<<dim3(512 / 128, MB), 256>>>(mid, ffn_w2, ffn_b2, h1, tmp, T, 512, 2048);
    ln_kernel<<<T, 256>>>(tmp, ln2_g, ln2_b, (float*)d_out);
}

// round 4
// speedup vs baseline: 3.2773x; 3.2773x over previous
#include <cuda_runtime.h>
#include <math.h>
#include <stdint.h>

// ---------------------------------------------------------------------------
// Problem constants: D=512, H=8, hd=64. T runtime (6144 in the fixed setup).
// ---------------------------------------------------------------------------
#define MAX_T 8192
#define MAX_TILES 1024

// Scratch (device globals; no allocation allowed)
__device__ float g_qk [MAX_T * 1024];  // [T, 1024]: q = [:,0:512], k = [:,512:1024]
__device__ float g_v  [MAX_T * 512];
__device__ float g_ctx[MAX_T * 512];
__device__ float g_tmp[MAX_T * 512];
__device__ float g_h1 [MAX_T * 512];
__device__ float g_mid[MAX_T * 2048];
__device__ float g_wt [3145728];       // transposed weights [N,K], tf32-rounded
__device__ int   g_tiles[MAX_TILES * 4]; // (qstart, qlen, kstart, klen)
__device__ int   g_meta[4];              // [0] = ntiles

// Transposed-weight offsets inside g_wt
#define WT_V    0
#define WT_QK   262144
#define WT_PROJ 786432
#define WT_FFN1 1048576
#define WT_FFN2 2097152

// ---------------------------------------------------------------------------
// PTX helpers (all sm_80-level: no 'a'-gated features)
// ---------------------------------------------------------------------------
__device__ __forceinline__ void cpa16(uint32_t dst, const void* src, int sz) {
    asm volatile("cp.async.cg.shared.global [%0], [%1], 16, %2;\n"
                 :: "r"(dst), "l"(src), "r"(sz) : "memory");
}
__device__ __forceinline__ void cp_commit() {
    asm volatile("cp.async.commit_group;\n" ::: "memory");
}
template <int N> __device__ __forceinline__ void cp_wait() {
    asm volatile("cp.async.wait_group %0;\n" :: "n"(N) : "memory");
}
__device__ __forceinline__ uint32_t smem_u32(const void* p) {
    uint32_t a;
    asm("{ .reg .u64 t; cvta.to.shared.u64 t, %1; cvt.u32.u64 %0, t; }"
        : "=r"(a) : "l"(p));
    return a;
}
__device__ __forceinline__ uint32_t f2tf32(float v) {
    uint32_t u;
    asm("cvt.rna.tf32.f32 %0, %1;" : "=r"(u) : "f"(v));
    return u;
}
__device__ __forceinline__ void mma_tf32_16n8k8(float c[4],
                                                uint32_t a0, uint32_t a1,
                                                uint32_t a2, uint32_t a3,
                                                uint32_t b0, uint32_t b1) {
    asm volatile(
        "mma.sync.aligned.m16n8k8.row.col.f32.tf32.tf32.f32 "
        "{%0,%1,%2,%3}, {%4,%5,%6,%7}, {%8,%9}, {%0,%1,%2,%3};"
        : "+f"(c[0]), "+f"(c[1]), "+f"(c[2]), "+f"(c[3])
        : "r"(a0), "r"(a1), "r"(a2), "r"(a3), "r"(b0), "r"(b1));
}

// ---------------------------------------------------------------------------
// Tile table builder (int32/int64 cumsum autodetect)
// ---------------------------------------------------------------------------
__global__ void build_tiles_kernel(const int* __restrict__ cum_raw, int T) {
    bool is64 = (cum_raw[1] == 0);
    int nt = 0;
    for (int s = 0; s < 256; ++s) {
        int start = is64 ? cum_raw[2 * s] : cum_raw[s];
        if (start >= T) break;
        int end = is64 ? cum_raw[2 * (s + 1)] : cum_raw[s + 1];
        int len = end - start;
        for (int q0 = 0; q0 < len && nt < MAX_TILES; q0 += 64) {
            g_tiles[nt * 4 + 0] = start + q0;
            g_tiles[nt * 4 + 1] = min(64, len - q0);
            g_tiles[nt * 4 + 2] = start;
            g_tiles[nt * 4 + 3] = len;
            ++nt;
        }
        if (end >= T) break;
    }
    g_meta[0] = nt;
}

// ---------------------------------------------------------------------------
// Weight transpose [K,N] -> [N,K], with round-to-nearest tf32.
// ---------------------------------------------------------------------------
__global__ void __launch_bounds__(256)
transpose_rna_kernel(const float* __restrict__ W, float* __restrict__ Wt,
                     int K, int N) {
    __shared__ float t[32][33];
    const int n0 = blockIdx.x * 32, k0 = blockIdx.y * 32;
    const int x = threadIdx.x, y = threadIdx.y;  // 32 x 8
#pragma unroll
    for (int i = 0; i < 32; i += 8)
        t[y + i][x] = W[(size_t)(k0 + y + i) * N + n0 + x];
    __syncthreads();
#pragma unroll
    for (int i = 0; i < 32; i += 8) {
        float v = t[x][y + i];
        Wt[(size_t)(n0 + y + i) * K + k0 + x] = __uint_as_float(f2tf32(v));
    }
}

// ---------------------------------------------------------------------------
// tf32 mma.sync GEMM: C[M,N] = A[M,K] @ Bt[N,K]^T + bias (+ epilogue)
// EPI: 0 = bias; 1 = bias + exact GELU; 2 = bias + residual add
// CTA tile 128x128, BK=32, 8 warps (32x64 warp tiles), double-buffer cp.async.
// Smem tile layout: 128 rows x 32 floats, row stride 36 (16B-aligned, no bank
// conflicts on fragment loads). Requires N % 128 == 0, K % 32 == 0.
// ---------------------------------------------------------------------------
#define RS        36                       // row stride (floats)
#define TILE_F    (128 * RS)               // floats per tile (A or B)
#define STAGE_F   (2 * TILE_F)             // floats per stage (A + B)
#define G_SMEM_BYTES (2 * STAGE_F * 4)     // 2 stages

template <int EPI>
__global__ void __launch_bounds__(256)
gemm_mma_kernel(const float* __restrict__ A, const float* __restrict__ Bt,
                const float* __restrict__ bias, const float* __restrict__ res,
                float* __restrict__ C, int M, int N, int K) {
    extern __shared__ float smf[];
    const uint32_t sb = smem_u32(smf);
    const int tid  = threadIdx.x;
    const int warp = tid >> 5;
    const int lane = tid & 31;
    const int bm = blockIdx.y * 128;
    const int bn = blockIdx.x * 128;

    const int g  = lane >> 2;   // group id 0..7
    const int tg = lane & 3;    // thread-in-group 0..3
    const int mr = (warp >> 1) * 32;   // warp row offset
    const int nc = (warp & 1) * 64;    // warp col offset

    float acc[2][8][4];
#pragma unroll
    for (int i = 0; i < 2; ++i)
#pragma unroll
        for (int j = 0; j < 8; ++j)
#pragma unroll
            for (int q = 0; q < 4; ++q) acc[i][j][q] = 0.f;

    const int nch = K >> 5;

    // Load chunk c into stage s. A tile at stage base, B tile at +TILE_F.
    auto load_chunk = [&](int c, int s) {
        const uint32_t abase = sb + (uint32_t)s * (STAGE_F * 4);
        const uint32_t bbase = abase + TILE_F * 4;
#pragma unroll
        for (int j = 0; j < 4; ++j) {
            int q = j * 256 + tid;        // 0..1023 (16B chunks)
            int r  = q >> 3;              // 0..127
            int kc = (q & 7) * 4;         // 0,4,...,28
            int gr = bm + r;
            const float* src = A + (size_t)min(gr, M - 1) * K + (size_t)c * 32 + kc;
            cpa16(abase + (uint32_t)(r * RS + kc) * 4, src, (gr < M) ? 16 : 0);
        }
#pragma unroll
        for (int j = 0; j < 4; ++j) {
            int q = j * 256 + tid;
            int r  = q >> 3;
            int kc = (q & 7) * 4;
            const float* src = Bt + (size_t)(bn + r) * K + (size_t)c * 32 + kc;
            cpa16(bbase + (uint32_t)(r * RS + kc) * 4, src, 16);
        }
        cp_commit();
    };

    load_chunk(0, 0);
    if (nch > 1) load_chunk(1, 1);
    else cp_commit();  // keep group count consistent

    for (int c = 0; c < nch; ++c) {
        const int s = c & 1;
        if (c + 1 < nch) cp_wait<1>(); else cp_wait<0>();
        __syncthreads();

        const float* As = smf + s * STAGE_F;
        const float* Bs = As + TILE_F;

#pragma unroll
        for (int kk = 0; kk < 32; kk += 8) {
            // A fragments (2 m-blocks x 4 regs), rna-converted to tf32
            uint32_t af[2][4];
#pragma unroll
            for (int mb = 0; mb < 2; ++mb) {
                const int r0 = mr + mb * 16 + g;
                af[mb][0] = f2tf32(As[(r0)     * RS + kk + tg]);
                af[mb][1] = f2tf32(As[(r0 + 8) * RS + kk + tg]);
                af[mb][2] = f2tf32(As[(r0)     * RS + kk + tg + 4]);
                af[mb][3] = f2tf32(As[(r0 + 8) * RS + kk + tg + 4]);
            }
            // B fragments per n-block (weights already tf32-rounded)
#pragma unroll
            for (int nb = 0; nb < 8; ++nb) {
                const int n0 = nc + nb * 8 + g;
                uint32_t b0 = __float_as_uint(Bs[n0 * RS + kk + tg]);
                uint32_t b1 = __float_as_uint(Bs[n0 * RS + kk + tg + 4]);
                mma_tf32_16n8k8(acc[0][nb], af[0][0], af[0][1], af[0][2], af[0][3], b0, b1);
                mma_tf32_16n8k8(acc[1][nb], af[1][0], af[1][1], af[1][2], af[1][3], b0, b1);
            }
        }
        __syncthreads();
        if (c + 2 < nch) load_chunk(c + 2, s);
        else cp_commit();
    }

    // Epilogue: thread owns (2 m-blocks) x (8 n-blocks) x (2 rows x 2 cols)
#pragma unroll
    for (int mb = 0; mb < 2; ++mb) {
#pragma unroll
        for (int rh = 0; rh < 2; ++rh) {
            const int gr = bm + mr + mb * 16 + rh * 8 + g;
            if (gr >= M) continue;
#pragma unroll
            for (int nb = 0; nb < 8; ++nb) {
                const int gc = bn + nc + nb * 8 + 2 * tg;
                float c0 = acc[mb][nb][rh * 2 + 0] + __ldg(bias + gc + 0);
                float c1 = acc[mb][nb][rh * 2 + 1] + __ldg(bias + gc + 1);
                if (EPI == 1) {
                    c0 = 0.5f * c0 * (1.0f + erff(c0 * 0.70710678118654752f));
                    c1 = 0.5f * c1 * (1.0f + erff(c1 * 0.70710678118654752f));
                } else if (EPI == 2) {
                    const float2 rr = *(const float2*)(res + (size_t)gr * N + gc);
                    c0 += rr.x; c1 += rr.y;
                }
                *(float2*)(C + (size_t)gr * N + gc) = make_float2(c0, c1);
            }
        }
    }
}

// ---------------------------------------------------------------------------
// Flash-style attention (fp32 SIMT; unchanged).
// ---------------------------------------------------------------------------
__global__ void __launch_bounds__(256)
attn_kernel(const float* __restrict__ qk, const float* __restrict__ v,
            float* __restrict__ ctx) {
    const int tile = blockIdx.x;
    if (tile >= g_meta[0]) return;
    const int h = blockIdx.y;

    const int qstart = g_tiles[tile * 4 + 0];
    const int qlen   = g_tiles[tile * 4 + 1];
    const int kstart = g_tiles[tile * 4 + 2];
    const int klen   = g_tiles[tile * 4 + 3];

    __shared__ float Qs[64][64];
    __shared__ float Ks[32][65];
    __shared__ float Vs[32][64];
    __shared__ float Ps[64][33];

    const int tid = threadIdx.x;
    const int tx  = tid & 15;
    const int ty  = tid >> 4;
    const int r0  = ty * 4;
    const int c0  = tx * 2;

#pragma unroll
    for (int p = 0; p < 4; ++p) {
        int l4 = tid + p * 256;
        int r  = l4 >> 4;
        int dc = (l4 & 15) * 4;
        float4 qv = make_float4(0.f, 0.f, 0.f, 0.f);
        if (r < qlen)
            qv = *(const float4*)(qk + (size_t)(qstart + r) * 1024 + h * 64 + dc);
        *(float4*)&Qs[r][dc] = qv;
    }

    float o[4][4];
    float m[4], l[4];
#pragma unroll
    for (int i = 0; i < 4; ++i) {
        m[i] = -1e30f; l[i] = 0.f;
#pragma unroll
        for (int j = 0; j < 4; ++j) o[i][j] = 0.f;
    }

    for (int kb = 0; kb < klen; kb += 32) {
        const int kn = min(32, klen - kb);
#pragma unroll
        for (int p = 0; p < 2; ++p) {
            int l4 = tid + p * 256;
            int r  = l4 >> 4;
            int dc = (l4 & 15) * 4;
            float4 kv = make_float4(0.f, 0.f, 0.f, 0.f);
            float4 vv = make_float4(0.f, 0.f, 0.f, 0.f);
            if (r < kn) {
                size_t t = (size_t)(kstart + kb + r);
                kv = *(const float4*)(qk + t * 1024 + 512 + h * 64 + dc);
                vv = *(const float4*)(v  + t * 512 + h * 64 + dc);
            }
            Ks[r][dc + 0] = kv.x; Ks[r][dc + 1] = kv.y;
            Ks[r][dc + 2] = kv.z; Ks[r][dc + 3] = kv.w;
            *(float4*)&Vs[r][dc] = vv;
        }
        __syncthreads();

        float s[4][2];
#pragma unroll
        for (int i = 0; i < 4; ++i) { s[i][0] = 0.f; s[i][1] = 0.f; }
#pragma unroll
        for (int d = 0; d < 64; d += 4) {
            float qv[4][4];
#pragma unroll
            for (int i = 0; i < 4; ++i)
                *(float4*)qv[i] = *(const float4*)&Qs[r0 + i][d];
            float k0v[4], k1v[4];
#pragma unroll
            for (int dd = 0; dd < 4; ++dd) {
                k0v[dd] = Ks[c0 + 0][d + dd];
                k1v[dd] = Ks[c0 + 1][d + dd];
            }
#pragma unroll
            for (int dd = 0; dd < 4; ++dd)
#pragma unroll
                for (int i = 0; i < 4; ++i) {
                    s[i][0] += qv[i][dd] * k0v[dd];
                    s[i][1] += qv[i][dd] * k1v[dd];
                }
        }

#pragma unroll
        for (int i = 0; i < 4; ++i) {
            float s0 = s[i][0] * 0.125f;
            float s1 = s[i][1] * 0.125f;
            if (kb + c0 + 0 >= klen) s0 = -1e30f;
            if (kb + c0 + 1 >= klen) s1 = -1e30f;
            float mb = fmaxf(s0, s1);
#pragma unroll
            for (int off = 8; off; off >>= 1)
                mb = fmaxf(mb, __shfl_xor_sync(0xffffffffu, mb, off));
            float mnew  = fmaxf(m[i], mb);
            float alpha = __expf(m[i] - mnew);
            float p0 = __expf(s0 - mnew);
            float p1 = __expf(s1 - mnew);
            float lb = p0 + p1;
#pragma unroll
            for (int off = 8; off; off >>= 1)
                lb += __shfl_xor_sync(0xffffffffu, lb, off);
            l[i] = l[i] * alpha + lb;
            m[i] = mnew;
#pragma unroll
            for (int j = 0; j < 4; ++j) o[i][j] *= alpha;
            Ps[r0 + i][c0 + 0] = p0;
            Ps[r0 + i][c0 + 1] = p1;
        }
        __syncthreads();

#pragma unroll
        for (int k = 0; k < 32; ++k) {
            float4 vv = *(const float4*)&Vs[k][tx * 4];
            float p0 = Ps[r0 + 0][k];
            float p1 = Ps[r0 + 1][k];
            float p2 = Ps[r0 + 2][k];
            float p3 = Ps[r0 + 3][k];
            o[0][0] += p0 * vv.x; o[0][1] += p0 * vv.y; o[0][2] += p0 * vv.z; o[0][3] += p0 * vv.w;
            o[1][0] += p1 * vv.x; o[1][1] += p1 * vv.y; o[1][2] += p1 * vv.z; o[1][3] += p1 * vv.w;
            o[2][0] += p2 * vv.x; o[2][1] += p2 * vv.y; o[2][2] += p2 * vv.z; o[2][3] += p2 * vv.w;
            o[3][0] += p3 * vv.x; o[3][1] += p3 * vv.y; o[3][2] += p3 * vv.z; o[3][3] += p3 * vv.w;
        }
        __syncthreads();
    }

#pragma unroll
    for (int i = 0; i < 4; ++i) {
        int r = r0 + i;
        if (r < qlen) {
            float inv = 1.0f / l[i];
            float4 out = make_float4(o[i][0] * inv, o[i][1] * inv,
                                     o[i][2] * inv, o[i][3] * inv);
            *(float4*)(ctx + (size_t)(qstart + r) * 512 + h * 64 + tx * 4) = out;
        }
    }
}

// ---------------------------------------------------------------------------
// Row-wise LayerNorm over D=512. One block per row, 256 threads.
// ---------------------------------------------------------------------------
__global__ void __launch_bounds__(256)
ln_kernel(const float* __restrict__ x, const float* __restrict__ g,
          const float* __restrict__ b, float* __restrict__ y) {
    const int row = blockIdx.x;
    const int tid = threadIdx.x;
    const float* xr = x + (size_t)row * 512;
    float v0 = xr[tid], v1 = xr[tid + 256];
    float s = v0 + v1;
    float q = v0 * v0 + v1 * v1;
#pragma unroll
    for (int off = 16; off; off >>= 1) {
        s += __shfl_xor_sync(0xffffffffu, s, off);
        q += __shfl_xor_sync(0xffffffffu, q, off);
    }
    __shared__ float ss[8], sq[8];
    int w = tid >> 5;
    if ((tid & 31) == 0) { ss[w] = s; sq[w] = q; }
    __syncthreads();
    if (tid < 32) {
        float s2 = (tid < 8) ? ss[tid] : 0.f;
        float q2 = (tid < 8) ? sq[tid] : 0.f;
#pragma unroll
        for (int off = 4; off; off >>= 1) {
            s2 += __shfl_xor_sync(0xffffffffu, s2, off);
            q2 += __shfl_xor_sync(0xffffffffu, q2, off);
        }
        if (tid == 0) { ss[0] = s2; sq[0] = q2; }
    }
    __syncthreads();
    float mean = ss[0] * (1.0f / 512.0f);
    float var  = sq[0] * (1.0f / 512.0f) - mean * mean;
    float rstd = rsqrtf(var + 1e-5f);
    y[(size_t)row * 512 + tid]       = (v0 - mean) * rstd * g[tid]       + b[tid];
    y[(size_t)row * 512 + tid + 256] = (v1 - mean) * rstd * g[tid + 256] + b[tid + 256];
}

// ---------------------------------------------------------------------------
// Launch
// ---------------------------------------------------------------------------
extern "C" void kernel_launch(void* const* d_in, const int* in_sizes, int n_in,
                              void* d_out, int out_size) {
    const float* h_n     = (const float*)d_in[0];
    const float* to_v_w  = (const float*)d_in[1];
    const float* to_v_b  = (const float*)d_in[2];
    const float* to_qk_w = (const float*)d_in[3];
    const float* to_qk_b = (const float*)d_in[4];
    const float* proj_w  = (const float*)d_in[5];
    const float* proj_b  = (const float*)d_in[6];
    const float* ffn_w1  = (const float*)d_in[7];
    const float* ffn_b1  = (const float*)d_in[8];
    const float* ffn_w2  = (const float*)d_in[9];
    const float* ffn_b2  = (const float*)d_in[10];
    const float* ln1_g   = (const float*)d_in[11];
    const float* ln1_b   = (const float*)d_in[12];
    const float* ln2_g   = (const float*)d_in[13];
    const float* ln2_b   = (const float*)d_in[14];
    const int*   cum     = (const int*)d_in[15];

    const int T = in_sizes[0] / 512;
    if (T <= 0 || T > MAX_T) return;

    float *qk, *v, *ctx, *tmp, *h1, *mid, *wt;
    cudaGetSymbolAddress((void**)&qk,  g_qk);
    cudaGetSymbolAddress((void**)&v,   g_v);
    cudaGetSymbolAddress((void**)&ctx, g_ctx);
    cudaGetSymbolAddress((void**)&tmp, g_tmp);
    cudaGetSymbolAddress((void**)&h1,  g_h1);
    cudaGetSymbolAddress((void**)&mid, g_mid);
    cudaGetSymbolAddress((void**)&wt,  g_wt);

    static bool attr_done = false;
    if (!attr_done) {
        cudaFuncSetAttribute(gemm_mma_kernel<0>,
            cudaFuncAttributeMaxDynamicSharedMemorySize, G_SMEM_BYTES);
        cudaFuncSetAttribute(gemm_mma_kernel<1>,
            cudaFuncAttributeMaxDynamicSharedMemorySize, G_SMEM_BYTES);
        cudaFuncSetAttribute(gemm_mma_kernel<2>,
            cudaFuncAttributeMaxDynamicSharedMemorySize, G_SMEM_BYTES);
        attr_done = true;
    }

    const int MB = (T + 127) / 128;

    // 0) tile table + weight transposes (tf32-rounded)
    build_tiles_kernel<<<1, 1>>>(cum, T);
    transpose_rna_kernel<<<dim3(512 / 32,  512 / 32),  dim3(32, 8)>>>(to_v_w,  wt + WT_V,    512, 512);
    transpose_rna_kernel<<<dim3(1024 / 32, 512 / 32),  dim3(32, 8)>>>(to_qk_w, wt + WT_QK,   512, 1024);
    transpose_rna_kernel<<<dim3(512 / 32,  512 / 32),  dim3(32, 8)>>>(proj_w,  wt + WT_PROJ, 512, 512);
    transpose_rna_kernel<<<dim3(2048 / 32, 512 / 32),  dim3(32, 8)>>>(ffn_w1,  wt + WT_FFN1, 512, 2048);
    transpose_rna_kernel<<<dim3(512 / 32,  2048 / 32), dim3(32, 8)>>>(ffn_w2,  wt + WT_FFN2, 2048, 512);

    // 1) v = h_n @ to_v_w + b ; qk = h_n @ to_qk_w + b
    gemm_mma_kernel<0><<<dim3(4, MB), 256, G_SMEM_BYTES>>>(h_n, wt + WT_V,  to_v_b,  nullptr, v,  T, 512,  512);
    gemm_mma_kernel<0><<<dim3(8, MB), 256, G_SMEM_BYTES>>>(h_n, wt + WT_QK, to_qk_b, nullptr, qk, T, 1024, 512);

    // 2) attention
    {
        int gx = (T + 63) / 64 + 64;
        attn_kernel<<<dim3(gx, 8), 256>>>(qk, v, ctx);
    }

    // 3) tmp = h_n + ctx @ proj_w + proj_b ; h1 = LN1(tmp)
    gemm_mma_kernel<2><<<dim3(4, MB), 256, G_SMEM_BYTES>>>(ctx, wt + WT_PROJ, proj_b, h_n, tmp, T, 512, 512);
    ln_kernel<<<T, 256>>>(tmp, ln1_g, ln1_b, h1);

    // 4) mid = gelu(h1 @ ffn_w1 + b1)
    gemm_mma_kernel<1><<<dim3(16, MB), 256, G_SMEM_BYTES>>>(h1, wt + WT_FFN1, ffn_b1, nullptr, mid, T, 2048, 512);

    // 5) tmp = h1 + mid @ ffn_w2 + b2 ; out = LN2(tmp)
    gemm_mma_kernel<2><<<dim3(4, MB), 256, G_SMEM_BYTES>>>(mid, wt + WT_FFN2, ffn_b2, h1, tmp, T, 512, 2048);
    ln_kernel<<<T, 256>>>(tmp, ln2_g, ln2_b, (float*)d_out);
}

// round 5
// speedup vs baseline: 4.9757x; 1.5183x over previous
#include <cuda_runtime.h>
#include <math.h>
#include <stdint.h>

// ---------------------------------------------------------------------------
// Problem constants: D=512, H=8, hd=64. T runtime (6144 in the fixed setup).
// ---------------------------------------------------------------------------
#define MAX_T 8192
#define MAX_TILES 1024

// Scratch (device globals; no allocation allowed)
__device__ float g_qk [MAX_T * 1024];  // [T, 1024]: q = [:,0:512], k = [:,512:1024]
__device__ float g_v  [MAX_T * 512];
__device__ float g_ctx[MAX_T * 512];
__device__ float g_tmp[MAX_T * 512];
__device__ float g_h1 [MAX_T * 512];
__device__ float g_mid[MAX_T * 2048];
__device__ float g_wt [3145728];       // transposed weights [N,K], tf32-rounded
__device__ int   g_tiles[MAX_TILES * 4]; // (qstart, qlen, kstart, klen)
__device__ int   g_meta[4];              // [0] = ntiles

// Transposed-weight offsets inside g_wt
#define WT_V    0
#define WT_QK   262144
#define WT_PROJ 786432
#define WT_FFN1 1048576
#define WT_FFN2 2097152

// ---------------------------------------------------------------------------
// PTX helpers (all sm_80-level: no 'a'-gated features)
// ---------------------------------------------------------------------------
__device__ __forceinline__ void cpa16(uint32_t dst, const void* src, int sz) {
    asm volatile("cp.async.cg.shared.global [%0], [%1], 16, %2;\n"
                 :: "r"(dst), "l"(src), "r"(sz) : "memory");
}
__device__ __forceinline__ void cp_commit() {
    asm volatile("cp.async.commit_group;\n" ::: "memory");
}
template <int N> __device__ __forceinline__ void cp_wait() {
    asm volatile("cp.async.wait_group %0;\n" :: "n"(N) : "memory");
}
__device__ __forceinline__ uint32_t smem_u32(const void* p) {
    uint32_t a;
    asm("{ .reg .u64 t; cvta.to.shared.u64 t, %1; cvt.u32.u64 %0, t; }"
        : "=r"(a) : "l"(p));
    return a;
}
__device__ __forceinline__ uint32_t f2tf32(float v) {
    uint32_t u;
    asm("cvt.rna.tf32.f32 %0, %1;" : "=r"(u) : "f"(v));
    return u;
}
__device__ __forceinline__ void mma_tf32_16n8k8(float c[4],
                                                uint32_t a0, uint32_t a1,
                                                uint32_t a2, uint32_t a3,
                                                uint32_t b0, uint32_t b1) {
    asm volatile(
        "mma.sync.aligned.m16n8k8.row.col.f32.tf32.tf32.f32 "
        "{%0,%1,%2,%3}, {%4,%5,%6,%7}, {%8,%9}, {%0,%1,%2,%3};"
        : "+f"(c[0]), "+f"(c[1]), "+f"(c[2]), "+f"(c[3])
        : "r"(a0), "r"(a1), "r"(a2), "r"(a3), "r"(b0), "r"(b1));
}

// ---------------------------------------------------------------------------
// Tile table builder (int32/int64 cumsum autodetect)
// ---------------------------------------------------------------------------
__global__ void build_tiles_kernel(const int* __restrict__ cum_raw, int T) {
    bool is64 = (cum_raw[1] == 0);
    int nt = 0;
    for (int s = 0; s < 256; ++s) {
        int start = is64 ? cum_raw[2 * s] : cum_raw[s];
        if (start >= T) break;
        int end = is64 ? cum_raw[2 * (s + 1)] : cum_raw[s + 1];
        int len = end - start;
        for (int q0 = 0; q0 < len && nt < MAX_TILES; q0 += 64) {
            g_tiles[nt * 4 + 0] = start + q0;
            g_tiles[nt * 4 + 1] = min(64, len - q0);
            g_tiles[nt * 4 + 2] = start;
            g_tiles[nt * 4 + 3] = len;
            ++nt;
        }
        if (end >= T) break;
    }
    g_meta[0] = nt;
}

// ---------------------------------------------------------------------------
// Weight transpose [K,N] -> [N,K], with round-to-nearest tf32.
// ---------------------------------------------------------------------------
__global__ void __launch_bounds__(256)
transpose_rna_kernel(const float* __restrict__ W, float* __restrict__ Wt,
                     int K, int N) {
    __shared__ float t[32][33];
    const int n0 = blockIdx.x * 32, k0 = blockIdx.y * 32;
    const int x = threadIdx.x, y = threadIdx.y;  // 32 x 8
#pragma unroll
    for (int i = 0; i < 32; i += 8)
        t[y + i][x] = W[(size_t)(k0 + y + i) * N + n0 + x];
    __syncthreads();
#pragma unroll
    for (int i = 0; i < 32; i += 8) {
        float v = t[x][y + i];
        Wt[(size_t)(n0 + y + i) * K + k0 + x] = __uint_as_float(f2tf32(v));
    }
}

// ---------------------------------------------------------------------------
// tf32 mma.sync GEMM: C[M,N] = A[M,K] @ Bt[N,K]^T + bias (+ epilogue)
// EPI: 0 = bias; 1 = bias + exact GELU; 2 = bias + residual add
// ---------------------------------------------------------------------------
#define RS        36
#define TILE_F    (128 * RS)
#define STAGE_F   (2 * TILE_F)
#define G_SMEM_BYTES (2 * STAGE_F * 4)

template <int EPI>
__global__ void __launch_bounds__(256)
gemm_mma_kernel(const float* __restrict__ A, const float* __restrict__ Bt,
                const float* __restrict__ bias, const float* __restrict__ res,
                float* __restrict__ C, int M, int N, int K) {
    extern __shared__ float smf[];
    const uint32_t sb = smem_u32(smf);
    const int tid  = threadIdx.x;
    const int warp = tid >> 5;
    const int lane = tid & 31;
    const int bm = blockIdx.y * 128;
    const int bn = blockIdx.x * 128;

    const int g  = lane >> 2;
    const int tg = lane & 3;
    const int mr = (warp >> 1) * 32;
    const int nc = (warp & 1) * 64;

    float acc[2][8][4];
#pragma unroll
    for (int i = 0; i < 2; ++i)
#pragma unroll
        for (int j = 0; j < 8; ++j)
#pragma unroll
            for (int q = 0; q < 4; ++q) acc[i][j][q] = 0.f;

    const int nch = K >> 5;

    auto load_chunk = [&](int c, int s) {
        const uint32_t abase = sb + (uint32_t)s * (STAGE_F * 4);
        const uint32_t bbase = abase + TILE_F * 4;
#pragma unroll
        for (int j = 0; j < 4; ++j) {
            int q = j * 256 + tid;
            int r  = q >> 3;
            int kc = (q & 7) * 4;
            int gr = bm + r;
            const float* src = A + (size_t)min(gr, M - 1) * K + (size_t)c * 32 + kc;
            cpa16(abase + (uint32_t)(r * RS + kc) * 4, src, (gr < M) ? 16 : 0);
        }
#pragma unroll
        for (int j = 0; j < 4; ++j) {
            int q = j * 256 + tid;
            int r  = q >> 3;
            int kc = (q & 7) * 4;
            const float* src = Bt + (size_t)(bn + r) * K + (size_t)c * 32 + kc;
            cpa16(bbase + (uint32_t)(r * RS + kc) * 4, src, 16);
        }
        cp_commit();
    };

    load_chunk(0, 0);
    if (nch > 1) load_chunk(1, 1);
    else cp_commit();

    for (int c = 0; c < nch; ++c) {
        const int s = c & 1;
        if (c + 1 < nch) cp_wait<1>(); else cp_wait<0>();
        __syncthreads();

        const float* As = smf + s * STAGE_F;
        const float* Bs = As + TILE_F;

#pragma unroll
        for (int kk = 0; kk < 32; kk += 8) {
            uint32_t af[2][4];
#pragma unroll
            for (int mb = 0; mb < 2; ++mb) {
                const int r0 = mr + mb * 16 + g;
                af[mb][0] = f2tf32(As[(r0)     * RS + kk + tg]);
                af[mb][1] = f2tf32(As[(r0 + 8) * RS + kk + tg]);
                af[mb][2] = f2tf32(As[(r0)     * RS + kk + tg + 4]);
                af[mb][3] = f2tf32(As[(r0 + 8) * RS + kk + tg + 4]);
            }
#pragma unroll
            for (int nb = 0; nb < 8; ++nb) {
                const int n0 = nc + nb * 8 + g;
                uint32_t b0 = __float_as_uint(Bs[n0 * RS + kk + tg]);
                uint32_t b1 = __float_as_uint(Bs[n0 * RS + kk + tg + 4]);
                mma_tf32_16n8k8(acc[0][nb], af[0][0], af[0][1], af[0][2], af[0][3], b0, b1);
                mma_tf32_16n8k8(acc[1][nb], af[1][0], af[1][1], af[1][2], af[1][3], b0, b1);
            }
        }
        __syncthreads();
        if (c + 2 < nch) load_chunk(c + 2, s);
        else cp_commit();
    }

#pragma unroll
    for (int mb = 0; mb < 2; ++mb) {
#pragma unroll
        for (int rh = 0; rh < 2; ++rh) {
            const int gr = bm + mr + mb * 16 + rh * 8 + g;
            if (gr >= M) continue;
#pragma unroll
            for (int nb = 0; nb < 8; ++nb) {
                const int gc = bn + nc + nb * 8 + 2 * tg;
                float c0 = acc[mb][nb][rh * 2 + 0] + __ldg(bias + gc + 0);
                float c1 = acc[mb][nb][rh * 2 + 1] + __ldg(bias + gc + 1);
                if (EPI == 1) {
                    c0 = 0.5f * c0 * (1.0f + erff(c0 * 0.70710678118654752f));
                    c1 = 0.5f * c1 * (1.0f + erff(c1 * 0.70710678118654752f));
                } else if (EPI == 2) {
                    const float2 rr = *(const float2*)(res + (size_t)gr * N + gc);
                    c0 += rr.x; c1 += rr.y;
                }
                *(float2*)(C + (size_t)gr * N + gc) = make_float2(c0, c1);
            }
        }
    }
}

// ---------------------------------------------------------------------------
// Tensor-core flash attention. Block = (64-row q-tile, head). 4 warps.
// Warp w owns q-rows [w*16, w*16+16). KV blocks of 64, double-buffered cp.async.
// S and PV both via m16n8k8 tf32 mma. Online softmax in C-fragment registers.
// P staged through per-warp-private smem rows (no cross-warp sync needed).
// Strides: AQ=68 floats (Q/K/P: conflict-free A/B frag loads), AV=72 (V).
// ---------------------------------------------------------------------------
#define AQ 68
#define AV 72
#define OFF_K (64 * AQ)                    // floats
#define OFF_V (OFF_K + 2 * 64 * AQ)
#define OFF_P (OFF_V + 2 * 64 * AV)
#define ATTN_SMEM_F (OFF_P + 64 * AQ)
#define ATTN_SMEM_BYTES (ATTN_SMEM_F * 4)

__global__ void __launch_bounds__(128)
attn_tc_kernel(const float* __restrict__ qk, const float* __restrict__ v,
               float* __restrict__ ctx) {
    extern __shared__ float sm[];
    const int tile = blockIdx.x;
    if (tile >= g_meta[0]) return;
    const int h = blockIdx.y;

    const int qstart = g_tiles[tile * 4 + 0];
    const int qlen   = g_tiles[tile * 4 + 1];
    const int kstart = g_tiles[tile * 4 + 2];
    const int klen   = g_tiles[tile * 4 + 3];

    float* Qs = sm;
    float* Ks = sm + OFF_K;
    float* Vs = sm + OFF_V;
    float* Ps = sm + OFF_P;
    const uint32_t sb = smem_u32(sm);

    const int tid  = threadIdx.x;
    const int warp = tid >> 5;
    const int lane = tid & 31;
    const int g  = lane >> 2;
    const int tg = lane & 3;
    const int wr = warp * 16;

    // Load Q (scale 0.125 folded in, rna tf32). Zero rows >= qlen.
#pragma unroll
    for (int j = 0; j < 8; ++j) {
        int i = j * 128 + tid;        // 0..1023 float4 slots
        int r = i >> 4, c = (i & 15) * 4;
        float4 qv = make_float4(0.f, 0.f, 0.f, 0.f);
        if (r < qlen)
            qv = *(const float4*)(qk + (size_t)(qstart + r) * 1024 + h * 64 + c);
        Qs[r * AQ + c + 0] = __uint_as_float(f2tf32(qv.x * 0.125f));
        Qs[r * AQ + c + 1] = __uint_as_float(f2tf32(qv.y * 0.125f));
        Qs[r * AQ + c + 2] = __uint_as_float(f2tf32(qv.z * 0.125f));
        Qs[r * AQ + c + 3] = __uint_as_float(f2tf32(qv.w * 0.125f));
    }

    // K/V stage loader (zero-fill rows beyond klen via src_size=0)
    auto loadKV = [&](int kb, int s) {
        const uint32_t kbase = sb + (OFF_K + s * 64 * AQ) * 4;
        const uint32_t vbase = sb + (OFF_V + s * 64 * AV) * 4;
#pragma unroll
        for (int j = 0; j < 8; ++j) {
            int i = j * 128 + tid;
            int r = i >> 4, c = (i & 15) * 4;
            int valid = (kb + r < klen) ? 16 : 0;
            size_t t = (size_t)(kstart + min(kb + r, klen - 1));
            cpa16(kbase + (uint32_t)(r * AQ + c) * 4,
                  qk + t * 1024 + 512 + h * 64 + c, valid);
            cpa16(vbase + (uint32_t)(r * AV + c) * 4,
                  v + t * 512 + h * 64 + c, valid);
        }
        cp_commit();
    };

    const int nkb = (klen + 63) >> 6;
    loadKV(0, 0);
    if (nkb > 1) loadKV(64, 1);
    else cp_commit();

    float O[8][4];
#pragma unroll
    for (int nb = 0; nb < 8; ++nb)
#pragma unroll
        for (int q = 0; q < 4; ++q) O[nb][q] = 0.f;
    float m0 = -1e30f, m1 = -1e30f, l0 = 0.f, l1 = 0.f;

    for (int ib = 0; ib < nkb; ++ib) {
        const int kb = ib * 64;
        const int s  = ib & 1;
        if (ib + 1 < nkb) cp_wait<1>(); else cp_wait<0>();
        __syncthreads();

        const float* Kst = Ks + s * 64 * AQ;
        const float* Vst = Vs + s * 64 * AV;

        // ---- S = Q @ K^T (C-fragments sf) ----
        float sf[8][4];
#pragma unroll
        for (int nb = 0; nb < 8; ++nb)
#pragma unroll
            for (int q = 0; q < 4; ++q) sf[nb][q] = 0.f;

#pragma unroll
        for (int kk = 0; kk < 64; kk += 8) {
            uint32_t a0 = __float_as_uint(Qs[(wr + g)     * AQ + kk + tg]);
            uint32_t a1 = __float_as_uint(Qs[(wr + g + 8) * AQ + kk + tg]);
            uint32_t a2 = __float_as_uint(Qs[(wr + g)     * AQ + kk + tg + 4]);
            uint32_t a3 = __float_as_uint(Qs[(wr + g + 8) * AQ + kk + tg + 4]);
#pragma unroll
            for (int nb = 0; nb < 8; ++nb) {
                uint32_t b0 = __float_as_uint(Kst[(nb * 8 + g) * AQ + kk + tg]);
                uint32_t b1 = __float_as_uint(Kst[(nb * 8 + g) * AQ + kk + tg + 4]);
                mma_tf32_16n8k8(sf[nb], a0, a1, a2, a3, b0, b1);
            }
        }

        // ---- online softmax (rows g and g+8 of this warp's 16-row block) ----
        float mx0 = -1e30f, mx1 = -1e30f;
#pragma unroll
        for (int nb = 0; nb < 8; ++nb) {
            int c0i = kb + nb * 8 + 2 * tg;
            if (c0i     >= klen) { sf[nb][0] = -1e30f; sf[nb][2] = -1e30f; }
            if (c0i + 1 >= klen) { sf[nb][1] = -1e30f; sf[nb][3] = -1e30f; }
            mx0 = fmaxf(mx0, fmaxf(sf[nb][0], sf[nb][1]));
            mx1 = fmaxf(mx1, fmaxf(sf[nb][2], sf[nb][3]));
        }
        mx0 = fmaxf(mx0, __shfl_xor_sync(0xffffffffu, mx0, 1));
        mx0 = fmaxf(mx0, __shfl_xor_sync(0xffffffffu, mx0, 2));
        mx1 = fmaxf(mx1, __shfl_xor_sync(0xffffffffu, mx1, 1));
        mx1 = fmaxf(mx1, __shfl_xor_sync(0xffffffffu, mx1, 2));

        const float mn0 = fmaxf(m0, mx0);
        const float mn1 = fmaxf(m1, mx1);
        const float al0 = __expf(m0 - mn0);
        const float al1 = __expf(m1 - mn1);
        float sum0 = 0.f, sum1 = 0.f;
#pragma unroll
        for (int nb = 0; nb < 8; ++nb) {
            sf[nb][0] = __uint_as_float(f2tf32(__expf(sf[nb][0] - mn0)));
            sf[nb][1] = __uint_as_float(f2tf32(__expf(sf[nb][1] - mn0)));
            sf[nb][2] = __uint_as_float(f2tf32(__expf(sf[nb][2] - mn1)));
            sf[nb][3] = __uint_as_float(f2tf32(__expf(sf[nb][3] - mn1)));
            sum0 += sf[nb][0] + sf[nb][1];
            sum1 += sf[nb][2] + sf[nb][3];
            *(float2*)&Ps[(wr + g)     * AQ + nb * 8 + 2 * tg] =
                make_float2(sf[nb][0], sf[nb][1]);
            *(float2*)&Ps[(wr + g + 8) * AQ + nb * 8 + 2 * tg] =
                make_float2(sf[nb][2], sf[nb][3]);
        }
        sum0 += __shfl_xor_sync(0xffffffffu, sum0, 1);
        sum0 += __shfl_xor_sync(0xffffffffu, sum0, 2);
        sum1 += __shfl_xor_sync(0xffffffffu, sum1, 1);
        sum1 += __shfl_xor_sync(0xffffffffu, sum1, 2);
        l0 = l0 * al0 + sum0;
        l1 = l1 * al1 + sum1;
        m0 = mn0; m1 = mn1;
#pragma unroll
        for (int nb = 0; nb < 8; ++nb) {
            O[nb][0] *= al0; O[nb][1] *= al0;
            O[nb][2] *= al1; O[nb][3] *= al1;
        }
        __syncwarp();

        // ---- O += P @ V ----
#pragma unroll
        for (int kk = 0; kk < 64; kk += 8) {
            uint32_t a0 = __float_as_uint(Ps[(wr + g)     * AQ + kk + tg]);
            uint32_t a1 = __float_as_uint(Ps[(wr + g + 8) * AQ + kk + tg]);
            uint32_t a2 = __float_as_uint(Ps[(wr + g)     * AQ + kk + tg + 4]);
            uint32_t a3 = __float_as_uint(Ps[(wr + g + 8) * AQ + kk + tg + 4]);
#pragma unroll
            for (int nb = 0; nb < 8; ++nb) {
                uint32_t b0 = __float_as_uint(Vst[(kk + tg)     * AV + nb * 8 + g]);
                uint32_t b1 = __float_as_uint(Vst[(kk + tg + 4) * AV + nb * 8 + g]);
                mma_tf32_16n8k8(O[nb], a0, a1, a2, a3, b0, b1);
            }
        }

        __syncthreads();   // all warps done with stage s before refilling it
        if (ib + 2 < nkb) loadKV((ib + 2) * 64, s);
    }

    // ---- write ctx ----
    const float inv0 = 1.0f / l0;
    const float inv1 = 1.0f / l1;
    const int r0 = wr + g, r1 = wr + g + 8;
#pragma unroll
    for (int nb = 0; nb < 8; ++nb) {
        const int gc = h * 64 + nb * 8 + 2 * tg;
        if (r0 < qlen)
            *(float2*)(ctx + (size_t)(qstart + r0) * 512 + gc) =
                make_float2(O[nb][0] * inv0, O[nb][1] * inv0);
        if (r1 < qlen)
            *(float2*)(ctx + (size_t)(qstart + r1) * 512 + gc) =
                make_float2(O[nb][2] * inv1, O[nb][3] * inv1);
    }
}

// ---------------------------------------------------------------------------
// Row-wise LayerNorm over D=512. One block per row, 256 threads.
// ---------------------------------------------------------------------------
__global__ void __launch_bounds__(256)
ln_kernel(const float* __restrict__ x, const float* __restrict__ g,
          const float* __restrict__ b, float* __restrict__ y) {
    const int row = blockIdx.x;
    const int tid = threadIdx.x;
    const float* xr = x + (size_t)row * 512;
    float v0 = xr[tid], v1 = xr[tid + 256];
    float s = v0 + v1;
    float q = v0 * v0 + v1 * v1;
#pragma unroll
    for (int off = 16; off; off >>= 1) {
        s += __shfl_xor_sync(0xffffffffu, s, off);
        q += __shfl_xor_sync(0xffffffffu, q, off);
    }
    __shared__ float ss[8], sq[8];
    int w = tid >> 5;
    if ((tid & 31) == 0) { ss[w] = s; sq[w] = q; }
    __syncthreads();
    if (tid < 32) {
        float s2 = (tid < 8) ? ss[tid] : 0.f;
        float q2 = (tid < 8) ? sq[tid] : 0.f;
#pragma unroll
        for (int off = 4; off; off >>= 1) {
            s2 += __shfl_xor_sync(0xffffffffu, s2, off);
            q2 += __shfl_xor_sync(0xffffffffu, q2, off);
        }
        if (tid == 0) { ss[0] = s2; sq[0] = q2; }
    }
    __syncthreads();
    float mean = ss[0] * (1.0f / 512.0f);
    float var  = sq[0] * (1.0f / 512.0f) - mean * mean;
    float rstd = rsqrtf(var + 1e-5f);
    y[(size_t)row * 512 + tid]       = (v0 - mean) * rstd * g[tid]       + b[tid];
    y[(size_t)row * 512 + tid + 256] = (v1 - mean) * rstd * g[tid + 256] + b[tid + 256];
}

// ---------------------------------------------------------------------------
// Launch
// ---------------------------------------------------------------------------
extern "C" void kernel_launch(void* const* d_in, const int* in_sizes, int n_in,
                              void* d_out, int out_size) {
    const float* h_n     = (const float*)d_in[0];
    const float* to_v_w  = (const float*)d_in[1];
    const float* to_v_b  = (const float*)d_in[2];
    const float* to_qk_w = (const float*)d_in[3];
    const float* to_qk_b = (const float*)d_in[4];
    const float* proj_w  = (const float*)d_in[5];
    const float* proj_b  = (const float*)d_in[6];
    const float* ffn_w1  = (const float*)d_in[7];
    const float* ffn_b1  = (const float*)d_in[8];
    const float* ffn_w2  = (const float*)d_in[9];
    const float* ffn_b2  = (const float*)d_in[10];
    const float* ln1_g   = (const float*)d_in[11];
    const float* ln1_b   = (const float*)d_in[12];
    const float* ln2_g   = (const float*)d_in[13];
    const float* ln2_b   = (const float*)d_in[14];
    const int*   cum     = (const int*)d_in[15];

    const int T = in_sizes[0] / 512;
    if (T <= 0 || T > MAX_T) return;

    float *qk, *v, *ctx, *tmp, *h1, *mid, *wt;
    cudaGetSymbolAddress((void**)&qk,  g_qk);
    cudaGetSymbolAddress((void**)&v,   g_v);
    cudaGetSymbolAddress((void**)&ctx, g_ctx);
    cudaGetSymbolAddress((void**)&tmp, g_tmp);
    cudaGetSymbolAddress((void**)&h1,  g_h1);
    cudaGetSymbolAddress((void**)&mid, g_mid);
    cudaGetSymbolAddress((void**)&wt,  g_wt);

    static bool attr_done = false;
    if (!attr_done) {
        cudaFuncSetAttribute(gemm_mma_kernel<0>,
            cudaFuncAttributeMaxDynamicSharedMemorySize, G_SMEM_BYTES);
        cudaFuncSetAttribute(gemm_mma_kernel<1>,
            cudaFuncAttributeMaxDynamicSharedMemorySize, G_SMEM_BYTES);
        cudaFuncSetAttribute(gemm_mma_kernel<2>,
            cudaFuncAttributeMaxDynamicSharedMemorySize, G_SMEM_BYTES);
        cudaFuncSetAttribute(attn_tc_kernel,
            cudaFuncAttributeMaxDynamicSharedMemorySize, ATTN_SMEM_BYTES);
        attr_done = true;
    }

    const int MB = (T + 127) / 128;

    // 0) tile table + weight transposes (tf32-rounded)
    build_tiles_kernel<<<1, 1>>>(cum, T);
    transpose_rna_kernel<<<dim3(512 / 32,  512 / 32),  dim3(32, 8)>>>(to_v_w,  wt + WT_V,    512, 512);
    transpose_rna_kernel<<<dim3(1024 / 32, 512 / 32),  dim3(32, 8)>>>(to_qk_w, wt + WT_QK,   512, 1024);
    transpose_rna_kernel<<<dim3(512 / 32,  512 / 32),  dim3(32, 8)>>>(proj_w,  wt + WT_PROJ, 512, 512);
    transpose_rna_kernel<<<dim3(2048 / 32, 512 / 32),  dim3(32, 8)>>>(ffn_w1,  wt + WT_FFN1, 512, 2048);
    transpose_rna_kernel<<<dim3(512 / 32,  2048 / 32), dim3(32, 8)>>>(ffn_w2,  wt + WT_FFN2, 2048, 512);

    // 1) v = h_n @ to_v_w + b ; qk = h_n @ to_qk_w + b
    gemm_mma_kernel<0><<<dim3(4, MB), 256, G_SMEM_BYTES>>>(h_n, wt + WT_V,  to_v_b,  nullptr, v,  T, 512,  512);
    gemm_mma_kernel<0><<<dim3(8, MB), 256, G_SMEM_BYTES>>>(h_n, wt + WT_QK, to_qk_b, nullptr, qk, T, 1024, 512);

    // 2) attention (tensor-core flash)
    {
        int gx = (T + 63) / 64 + 64;
        attn_tc_kernel<<<dim3(gx, 8), 128, ATTN_SMEM_BYTES>>>(qk, v, ctx);
    }

    // 3) tmp = h_n + ctx @ proj_w + proj_b ; h1 = LN1(tmp)
    gemm_mma_kernel<2><<<dim3(4, MB), 256, G_SMEM_BYTES>>>(ctx, wt + WT_PROJ, proj_b, h_n, tmp, T, 512, 512);
    ln_kernel<<<T, 256>>>(tmp, ln1_g, ln1_b, h1);

    // 4) mid = gelu(h1 @ ffn_w1 + b1)
    gemm_mma_kernel<1><<<dim3(16, MB), 256, G_SMEM_BYTES>>>(h1, wt + WT_FFN1, ffn_b1, nullptr, mid, T, 2048, 512);

    // 5) tmp = h1 + mid @ ffn_w2 + b2 ; out = LN2(tmp)
    gemm_mma_kernel<2><<<dim3(4, MB), 256, G_SMEM_BYTES>>>(mid, wt + WT_FFN2, ffn_b2, h1, tmp, T, 512, 2048);
    ln_kernel<<<T, 256>>>(tmp, ln2_g, ln2_b, (float*)d_out);
}